// round 8
// baseline (speedup 1.0000x reference)
#include <cuda_runtime.h>
#include <cuda_bf16.h>
#include <math.h>

// Problem constants
#define BB 2
#define LL 2048
#define DDIM 1024
#define NH 16
#define NKV 4
#define HD 64
#define WIN 1024

// -------- device scratch (allocation-free rule: __device__ globals) --------
__device__ float g_q [BB*LL*DDIM];        // x @ Wq         [4096,1024]
__device__ float g_k [BB*LL*NKV*HD];      // x @ Wk         [4096,256]
__device__ float g_v [BB*LL*NKV*HD];      // x @ Wv         [4096,256]
__device__ float g_Qr[BB*NH*LL*HD];       // rope(q)*scale  [b,h,l,d]
__device__ float g_Kr[BB*NKV*LL*HD];      // rope(k)        [b,kv,l,d]
__device__ float g_Vt[BB*NKV*HD*LL];      // v transposed   [b,kv,d,l]
__device__ float g_O [BB*LL*NH*HD];       // attn out       [b,l,h*d]

// round-to-nearest fp32 -> tf32 (keeps value as float with low mantissa cleared)
__device__ __forceinline__ float tf32r(float x){
    unsigned u; asm("cvt.rna.tf32.f32 %0, %1;" : "=r"(u) : "f"(x));
    return __uint_as_float(u);
}

#define MMA8(d, a, b0_, b1_) asm volatile( \
    "mma.sync.aligned.m16n8k8.row.col.f32.tf32.tf32.f32 " \
    "{%0,%1,%2,%3},{%4,%5,%6,%7},{%8,%9},{%0,%1,%2,%3};\n" \
    : "+f"(d[0]), "+f"(d[1]), "+f"(d[2]), "+f"(d[3]) \
    : "r"(a[0]), "r"(a[1]), "r"(a[2]), "r"(a[3]), "r"(b0_), "r"(b1_))

__device__ __forceinline__ void st4cvt(float* p, float4 v){
    float4 w = make_float4(tf32r(v.x), tf32r(v.y), tf32r(v.z), tf32r(v.w));
    *reinterpret_cast<float4*>(p) = w;
}

// ============================================================================
// TF32 GEMM: C[M,N] = A[M,K] @ B[K,N], all row-major, M%128==0, N%128==0, K%16==0
// CTA tile 128x128x16, 256 threads (8 warps, warp tile 64x32), double-buffered.
// ============================================================================
__global__ __launch_bounds__(256) void gemm_tf32(
    const float* __restrict__ A, const float* __restrict__ Bm, float* __restrict__ C,
    int M, int N, int K)
{
    __shared__ __align__(16) float As[2][128][20];   // stride 20: conflict-free A frags
    __shared__ __align__(16) float Bs[2][16][136];   // stride 136: conflict-free B frags

    const int tid  = threadIdx.x;
    const int m0   = blockIdx.y * 128;
    const int n0   = blockIdx.x * 128;
    const int ar   = tid >> 2,  ac = (tid & 3) << 2;   // A tile loader mapping
    const int br   = tid >> 5,  bc = (tid & 31) << 2;  // B tile loader mapping
    const int lane = tid & 31,  wid = tid >> 5;
    const int g    = lane >> 2, tg  = lane & 3;
    const int wm   = wid >> 2,  wn  = wid & 3;         // warp grid 2(M) x 4(N)

    float acc[4][4][4];
    #pragma unroll
    for (int i = 0; i < 4; i++)
        #pragma unroll
        for (int j = 0; j < 4; j++)
            #pragma unroll
            for (int e = 0; e < 4; e++) acc[i][j][e] = 0.f;

    // preload chunk 0
    {
        float4 ra0 = *reinterpret_cast<const float4*>(&A[(m0+ar   )*K + ac]);
        float4 ra1 = *reinterpret_cast<const float4*>(&A[(m0+ar+64)*K + ac]);
        float4 rb0 = *reinterpret_cast<const float4*>(&Bm[(br  )*N + n0 + bc]);
        float4 rb1 = *reinterpret_cast<const float4*>(&Bm[(br+8)*N + n0 + bc]);
        st4cvt(&As[0][ar   ][ac], ra0);
        st4cvt(&As[0][ar+64][ac], ra1);
        st4cvt(&Bs[0][br  ][bc], rb0);
        st4cvt(&Bs[0][br+8][bc], rb1);
    }
    __syncthreads();

    const int nk = K >> 4;
    int p = 0;
    for (int kc = 0; kc < nk; kc++) {
        float4 ra0, ra1, rb0, rb1;
        const bool hn = (kc + 1) < nk;
        if (hn) {
            int k0 = (kc + 1) << 4;
            ra0 = *reinterpret_cast<const float4*>(&A[(m0+ar   )*K + k0 + ac]);
            ra1 = *reinterpret_cast<const float4*>(&A[(m0+ar+64)*K + k0 + ac]);
            rb0 = *reinterpret_cast<const float4*>(&Bm[(k0+br  )*N + n0 + bc]);
            rb1 = *reinterpret_cast<const float4*>(&Bm[(k0+br+8)*N + n0 + bc]);
        }
        #pragma unroll
        for (int s = 0; s < 2; s++) {
            unsigned af[4][4];
            #pragma unroll
            for (int i = 0; i < 4; i++) {
                int mr = wm*64 + i*16;
                af[i][0] = __float_as_uint(As[p][mr+g  ][s*8+tg  ]);
                af[i][1] = __float_as_uint(As[p][mr+g+8][s*8+tg  ]);
                af[i][2] = __float_as_uint(As[p][mr+g  ][s*8+tg+4]);
                af[i][3] = __float_as_uint(As[p][mr+g+8][s*8+tg+4]);
            }
            #pragma unroll
            for (int j = 0; j < 4; j++) {
                int nb = wn*32 + j*8;
                unsigned b0 = __float_as_uint(Bs[p][s*8+tg  ][nb+g]);
                unsigned b1 = __float_as_uint(Bs[p][s*8+tg+4][nb+g]);
                #pragma unroll
                for (int i = 0; i < 4; i++) MMA8(acc[i][j], af[i], b0, b1);
            }
        }
        if (hn) {
            st4cvt(&As[p^1][ar   ][ac], ra0);
            st4cvt(&As[p^1][ar+64][ac], ra1);
            st4cvt(&Bs[p^1][br  ][bc], rb0);
            st4cvt(&Bs[p^1][br+8][bc], rb1);
        }
        __syncthreads();
        p ^= 1;
    }

    #pragma unroll
    for (int i = 0; i < 4; i++) {
        int r = m0 + wm*64 + i*16 + g;
        #pragma unroll
        for (int j = 0; j < 4; j++) {
            int c = n0 + wn*32 + j*8 + 2*tg;
            C[r*N + c]       = acc[i][j][0];
            C[r*N + c + 1]   = acc[i][j][1];
            C[(r+8)*N + c]     = acc[i][j][2];
            C[(r+8)*N + c + 1] = acc[i][j][3];
        }
    }
}

// ============================================================================
// RoPE + scatter: q -> Qr (scaled by 1/8, tf32), k -> Kr (tf32), v -> Vt (tf32)
// ============================================================================
__global__ __launch_bounds__(256) void rope_scatter()
{
    const int QN = BB*LL*NH*HD;    // 4194304
    const int KN = BB*LL*NKV*HD;   // 1048576
    const int VN = KN;
    int t = blockIdx.x * blockDim.x + threadIdx.x;

    if (t < QN) {
        int d = t & 63, h = (t >> 6) & 15, l = (t >> 10) & 2047, b = t >> 21;
        const float* row = g_q + (b*LL + l)*DDIM + h*HD;
        float val  = row[d];
        float part = (d < 32) ? -row[d + 32] : row[d - 32];
        int   i    = d & 31;
        float inv  = 1.0f / powf(10000.0f, (float)i * (1.0f/32.0f));
        float ang  = (float)l * inv;
        float sn, cs; sincosf(ang, &sn, &cs);
        float outv = (val*cs + part*sn) * 0.125f;   // fold softmax scale 1/sqrt(64)
        g_Qr[((b*NH + h)*LL + l)*HD + d] = tf32r(outv);
    } else if (t < QN + KN) {
        int u = t - QN;
        int d = u & 63, h = (u >> 6) & 3, l = (u >> 8) & 2047, b = u >> 19;
        const float* row = g_k + (b*LL + l)*(NKV*HD) + h*HD;
        float val  = row[d];
        float part = (d < 32) ? -row[d + 32] : row[d - 32];
        int   i    = d & 31;
        float inv  = 1.0f / powf(10000.0f, (float)i * (1.0f/32.0f));
        float ang  = (float)l * inv;
        float sn, cs; sincosf(ang, &sn, &cs);
        g_Kr[((b*NKV + h)*LL + l)*HD + d] = tf32r(val*cs + part*sn);
    } else if (t < QN + KN + VN) {
        int u = t - QN - KN;
        int l = u & 2047, d = (u >> 11) & 63, h = (u >> 17) & 3, b = u >> 19;
        g_Vt[((b*NKV + h)*HD + d)*LL + l] =
            tf32r(g_v[(b*LL + l)*(NKV*HD) + h*HD + d]);
    }
}

// ============================================================================
// Sliding-window flash attention. CTA = (qtile of 64, head, batch), 4 warps.
// Warp owns 16 query rows. QK^T and PV via mma.m16n8k8.tf32, softmax fp32.
// ============================================================================
__global__ __launch_bounds__(128) void attn_kernel()
{
    __shared__ __align__(16) float Ks[64][68];  // K tile  [j][d], stride 68 -> conflict-free
    __shared__ __align__(16) float Vs[64][68];  // V^T tile [d][j]

    const int qt0 = blockIdx.x * 64;
    const int h   = blockIdx.y;
    const int b   = blockIdx.z;
    const int kv  = h >> 2;

    const int tid = threadIdx.x, w = tid >> 5, lane = tid & 31;
    const int g = lane >> 2, tg = lane & 3;

    const float* Qb = g_Qr + (size_t)((b*NH  + h )*LL)*HD;
    const float* Kb = g_Kr + (size_t)((b*NKV + kv)*LL)*HD;
    const float* Vb = g_Vt + (size_t)((b*NKV + kv)*HD)*LL;

    const int qr = qt0 + w*16;

    // Q fragments (already tf32-rounded + scaled), held for whole CTA lifetime
    unsigned aq[8][4];
    #pragma unroll
    for (int s = 0; s < 8; s++) {
        aq[s][0] = __float_as_uint(Qb[(qr+g  )*HD + 8*s+tg  ]);
        aq[s][1] = __float_as_uint(Qb[(qr+g+8)*HD + 8*s+tg  ]);
        aq[s][2] = __float_as_uint(Qb[(qr+g  )*HD + 8*s+tg+4]);
        aq[s][3] = __float_as_uint(Qb[(qr+g+8)*HD + 8*s+tg+4]);
    }

    float o[8][4];
    #pragma unroll
    for (int dn = 0; dn < 8; dn++)
        #pragma unroll
        for (int e = 0; e < 4; e++) o[dn][e] = 0.f;
    float m0 = -1e30f, m1 = -1e30f, l0 = 0.f, l1 = 0.f;

    const int i0 = qt0 + w*16 + g;
    const int i1 = i0 + 8;

    int lo = qt0 - (WIN - 1); if (lo < 0) lo = 0;
    const int kt_lo = lo >> 6;
    const int kt_hi = qt0 >> 6;

    for (int kt = kt_lo; kt <= kt_hi; kt++) {
        const int j0 = kt << 6;
        __syncthreads();
        for (int idx = tid; idx < 64*16; idx += 128) {
            int r = idx >> 4, c4 = (idx & 15) << 2;
            *reinterpret_cast<float4*>(&Ks[r][c4]) =
                *reinterpret_cast<const float4*>(&Kb[(j0+r)*HD + c4]);
            *reinterpret_cast<float4*>(&Vs[r][c4]) =
                *reinterpret_cast<const float4*>(&Vb[r*LL + j0 + c4]);
        }
        __syncthreads();

        // ---- S = Q K^T ----
        float sc[8][4];
        #pragma unroll
        for (int jn = 0; jn < 8; jn++) {
            sc[jn][0] = sc[jn][1] = sc[jn][2] = sc[jn][3] = 0.f;
            const int jb = jn*8 + g;
            #pragma unroll
            for (int s = 0; s < 8; s++) {
                unsigned b0 = __float_as_uint(Ks[jb][8*s+tg  ]);
                unsigned b1 = __float_as_uint(Ks[jb][8*s+tg+4]);
                MMA8(sc[jn], aq[s], b0, b1);
            }
        }

        // ---- sliding-window causal mask ----
        #pragma unroll
        for (int jn = 0; jn < 8; jn++) {
            int j = j0 + jn*8 + 2*tg;
            if (!((j   <= i0) && (i0 - j     < WIN))) sc[jn][0] = -1e30f;
            if (!((j+1 <= i0) && (i0 - (j+1) < WIN))) sc[jn][1] = -1e30f;
            if (!((j   <= i1) && (i1 - j     < WIN))) sc[jn][2] = -1e30f;
            if (!((j+1 <= i1) && (i1 - (j+1) < WIN))) sc[jn][3] = -1e30f;
        }

        // ---- online softmax (fp32) ----
        float mx0 = -1e30f, mx1 = -1e30f;
        #pragma unroll
        for (int jn = 0; jn < 8; jn++) {
            mx0 = fmaxf(mx0, fmaxf(sc[jn][0], sc[jn][1]));
            mx1 = fmaxf(mx1, fmaxf(sc[jn][2], sc[jn][3]));
        }
        mx0 = fmaxf(mx0, __shfl_xor_sync(0xffffffffu, mx0, 1));
        mx0 = fmaxf(mx0, __shfl_xor_sync(0xffffffffu, mx0, 2));
        mx1 = fmaxf(mx1, __shfl_xor_sync(0xffffffffu, mx1, 1));
        mx1 = fmaxf(mx1, __shfl_xor_sync(0xffffffffu, mx1, 2));

        const float f0  = (mx0 > -1e29f) ? 1.f : 0.f;   // guard fully-masked rows
        const float f1  = (mx1 > -1e29f) ? 1.f : 0.f;
        const float mn0 = fmaxf(m0, mx0), mn1 = fmaxf(m1, mx1);
        const float al0 = __expf(m0 - mn0), al1 = __expf(m1 - mn1);

        float rs0 = 0.f, rs1 = 0.f;
        #pragma unroll
        for (int jn = 0; jn < 8; jn++) {
            float p0 = f0 * __expf(sc[jn][0] - mn0);
            float p1 = f0 * __expf(sc[jn][1] - mn0);
            float p2 = f1 * __expf(sc[jn][2] - mn1);
            float p3 = f1 * __expf(sc[jn][3] - mn1);
            sc[jn][0] = p0; sc[jn][1] = p1; sc[jn][2] = p2; sc[jn][3] = p3;
            rs0 += p0 + p1; rs1 += p2 + p3;
        }
        rs0 += __shfl_xor_sync(0xffffffffu, rs0, 1);
        rs0 += __shfl_xor_sync(0xffffffffu, rs0, 2);
        rs1 += __shfl_xor_sync(0xffffffffu, rs1, 1);
        rs1 += __shfl_xor_sync(0xffffffffu, rs1, 2);

        l0 = l0*al0 + rs0;  l1 = l1*al1 + rs1;
        m0 = mn0;           m1 = mn1;

        #pragma unroll
        for (int dn = 0; dn < 8; dn++) {
            o[dn][0] *= al0; o[dn][1] *= al0;
            o[dn][2] *= al1; o[dn][3] *= al1;
        }

        // ---- O += P V : convert P (C-layout) to A-layout via intra-group shuffles
        #pragma unroll
        for (int s = 0; s < 8; s++) {
            const int src1 = (g << 2) | (tg >> 1);
            const int src2 = (g << 2) | ((tg >> 1) + 2);
            float v00 = __shfl_sync(0xffffffffu, sc[s][0], src1);
            float v01 = __shfl_sync(0xffffffffu, sc[s][1], src1);
            float v10 = __shfl_sync(0xffffffffu, sc[s][2], src1);
            float v11 = __shfl_sync(0xffffffffu, sc[s][3], src1);
            float w00 = __shfl_sync(0xffffffffu, sc[s][0], src2);
            float w01 = __shfl_sync(0xffffffffu, sc[s][1], src2);
            float w10 = __shfl_sync(0xffffffffu, sc[s][2], src2);
            float w11 = __shfl_sync(0xffffffffu, sc[s][3], src2);
            const bool odd = (tg & 1);
            unsigned pa[4];
            pa[0] = __float_as_uint(tf32r(odd ? v01 : v00));
            pa[1] = __float_as_uint(tf32r(odd ? v11 : v10));
            pa[2] = __float_as_uint(tf32r(odd ? w01 : w00));
            pa[3] = __float_as_uint(tf32r(odd ? w11 : w10));
            #pragma unroll
            for (int dn = 0; dn < 8; dn++) {
                unsigned b0 = __float_as_uint(Vs[dn*8+g][8*s+tg  ]);
                unsigned b1 = __float_as_uint(Vs[dn*8+g][8*s+tg+4]);
                MMA8(o[dn], pa, b0, b1);
            }
        }
    }

    // ---- epilogue: normalize, write O in [b, l, h*64] layout ----
    const float il0 = 1.f / l0;
    const float il1 = 1.f / l1;
    #pragma unroll
    for (int dn = 0; dn < 8; dn++) {
        int dc = h*HD + dn*8 + 2*tg;
        g_O[(b*LL + i0)*(NH*HD) + dc]     = o[dn][0] * il0;
        g_O[(b*LL + i0)*(NH*HD) + dc + 1] = o[dn][1] * il0;
        g_O[(b*LL + i1)*(NH*HD) + dc]     = o[dn][2] * il1;
        g_O[(b*LL + i1)*(NH*HD) + dc + 1] = o[dn][3] * il1;
    }
}

// ============================================================================
extern "C" void kernel_launch(void* const* d_in, const int* in_sizes, int n_in,
                              void* d_out, int out_size)
{
    const float* x  = (const float*)d_in[0];
    const float* Wq = (const float*)d_in[1];
    const float* Wk = (const float*)d_in[2];
    const float* Wv = (const float*)d_in[3];
    const float* Wo = (const float*)d_in[4];
    float* out = (float*)d_out;

    float *pq, *pk, *pv, *pO;
    cudaGetSymbolAddress((void**)&pq, g_q);
    cudaGetSymbolAddress((void**)&pk, g_k);
    cudaGetSymbolAddress((void**)&pv, g_v);
    cudaGetSymbolAddress((void**)&pO, g_O);

    const int M = BB * LL;  // 4096

    gemm_tf32<<<dim3(DDIM/128,      M/128), 256>>>(x,  Wq, pq, M, DDIM,    DDIM);
    gemm_tf32<<<dim3((NKV*HD)/128,  M/128), 256>>>(x,  Wk, pk, M, NKV*HD,  DDIM);
    gemm_tf32<<<dim3((NKV*HD)/128,  M/128), 256>>>(x,  Wv, pv, M, NKV*HD,  DDIM);

    const int tot = BB*LL*NH*HD + 2*BB*LL*NKV*HD;  // 6291456
    rope_scatter<<<(tot + 255)/256, 256>>>();

    attn_kernel<<<dim3(LL/64, NH, BB), 128>>>();

    gemm_tf32<<<dim3(DDIM/128, M/128), 256>>>(pO, Wo, out, M, DDIM, DDIM);
}

// round 12
// speedup vs baseline: 1.2360x; 1.2360x over previous
#include <cuda_runtime.h>
#include <cuda_bf16.h>
#include <math.h>

// Problem constants
#define BB 2
#define LL 2048
#define DDIM 1024
#define NH 16
#define NKV 4
#define HD 64
#define WIN 1024
#define NQKV 1536   // 1024 (Q) + 256 (K) + 256 (V)

// -------- device scratch (allocation-free rule: __device__ globals) --------
__device__ float g_Wqkv[DDIM*NQKV];       // packed [Wq | Wk | Wv]  [1024,1536]
__device__ float g_qkv [BB*LL*NQKV];      // x @ Wqkv               [4096,1536]
__device__ float g_Qr[BB*NH*LL*HD];       // rope(q)*scale  [b,h,l,d]
__device__ float g_Kr[BB*NKV*LL*HD];      // rope(k)        [b,kv,l,d]
__device__ float g_Vt[BB*NKV*HD*LL];      // v transposed   [b,kv,d,l]
__device__ float g_O [BB*LL*NH*HD];       // attn out       [b,l,h*d]

// round-to-nearest fp32 -> tf32
__device__ __forceinline__ float tf32r(float x){
    unsigned u; asm("cvt.rna.tf32.f32 %0, %1;" : "=r"(u) : "f"(x));
    return __uint_as_float(u);
}

#define MMA8(d, a, b0_, b1_) asm volatile( \
    "mma.sync.aligned.m16n8k8.row.col.f32.tf32.tf32.f32 " \
    "{%0,%1,%2,%3},{%4,%5,%6,%7},{%8,%9},{%0,%1,%2,%3};\n" \
    : "+f"(d[0]), "+f"(d[1]), "+f"(d[2]), "+f"(d[3]) \
    : "r"(a[0]), "r"(a[1]), "r"(a[2]), "r"(a[3]), "r"(b0_), "r"(b1_))

__device__ __forceinline__ void st4cvt(float* p, float4 v){
    float4 w = make_float4(tf32r(v.x), tf32r(v.y), tf32r(v.z), tf32r(v.w));
    *reinterpret_cast<float4*>(p) = w;
}

// cp.async helpers
__device__ __forceinline__ void cpa16(float* dst, const float* src){
    unsigned d = (unsigned)__cvta_generic_to_shared(dst);
    asm volatile("cp.async.cg.shared.global [%0], [%1], 16;\n" :: "r"(d), "l"(src));
}
#define CPA_COMMIT asm volatile("cp.async.commit_group;\n" ::: "memory")
#define CPA_WAIT1  asm volatile("cp.async.wait_group 1;\n" ::: "memory")
#define CPA_WAIT0  asm volatile("cp.async.wait_group 0;\n" ::: "memory")

// ============================================================================
// Pack Wq|Wk|Wv into one [1024,1536] row-major weight (float4 granularity)
// ============================================================================
__global__ __launch_bounds__(256) void pack_w(
    const float* __restrict__ Wq, const float* __restrict__ Wk,
    const float* __restrict__ Wv)
{
    int t = blockIdx.x * 256 + threadIdx.x;      // < 1024*1536/4 = 393216
    int r = t / 384;
    int c = (t - r * 384) * 4;
    float4 v;
    if (c < 1024)      v = *reinterpret_cast<const float4*>(&Wq[r*1024 + c]);
    else if (c < 1280) v = *reinterpret_cast<const float4*>(&Wk[r*256 + c - 1024]);
    else               v = *reinterpret_cast<const float4*>(&Wv[r*256 + c - 1280]);
    *reinterpret_cast<float4*>(&g_Wqkv[r*NQKV + c]) = v;
}

// ============================================================================
// TF32 GEMM: C[M,N] = A[M,K] @ B[K,N], row-major, M%128==0, N%128==0, K%16==0
// CTA tile 128x128x16, 256 threads (8 warps, warp tile 64x32), double-buffered.
// ============================================================================
__global__ __launch_bounds__(256) void gemm_tf32(
    const float* __restrict__ A, const float* __restrict__ Bm, float* __restrict__ C,
    int M, int N, int K)
{
    __shared__ __align__(16) float As[2][128][20];
    __shared__ __align__(16) float Bs[2][16][136];

    const int tid  = threadIdx.x;
    const int m0   = blockIdx.y * 128;
    const int n0   = blockIdx.x * 128;
    const int ar   = tid >> 2,  ac = (tid & 3) << 2;
    const int br   = tid >> 5,  bc = (tid & 31) << 2;
    const int lane = tid & 31,  wid = tid >> 5;
    const int g    = lane >> 2, tg  = lane & 3;
    const int wm   = wid >> 2,  wn  = wid & 3;

    float acc[4][4][4];
    #pragma unroll
    for (int i = 0; i < 4; i++)
        #pragma unroll
        for (int j = 0; j < 4; j++)
            #pragma unroll
            for (int e = 0; e < 4; e++) acc[i][j][e] = 0.f;

    {
        float4 ra0 = *reinterpret_cast<const float4*>(&A[(m0+ar   )*K + ac]);
        float4 ra1 = *reinterpret_cast<const float4*>(&A[(m0+ar+64)*K + ac]);
        float4 rb0 = *reinterpret_cast<const float4*>(&Bm[(br  )*N + n0 + bc]);
        float4 rb1 = *reinterpret_cast<const float4*>(&Bm[(br+8)*N + n0 + bc]);
        st4cvt(&As[0][ar   ][ac], ra0);
        st4cvt(&As[0][ar+64][ac], ra1);
        st4cvt(&Bs[0][br  ][bc], rb0);
        st4cvt(&Bs[0][br+8][bc], rb1);
    }
    __syncthreads();

    const int nk = K >> 4;
    int p = 0;
    for (int kc = 0; kc < nk; kc++) {
        float4 ra0, ra1, rb0, rb1;
        const bool hn = (kc + 1) < nk;
        if (hn) {
            int k0 = (kc + 1) << 4;
            ra0 = *reinterpret_cast<const float4*>(&A[(m0+ar   )*K + k0 + ac]);
            ra1 = *reinterpret_cast<const float4*>(&A[(m0+ar+64)*K + k0 + ac]);
            rb0 = *reinterpret_cast<const float4*>(&Bm[(k0+br  )*N + n0 + bc]);
            rb1 = *reinterpret_cast<const float4*>(&Bm[(k0+br+8)*N + n0 + bc]);
        }
        #pragma unroll
        for (int s = 0; s < 2; s++) {
            unsigned af[4][4];
            #pragma unroll
            for (int i = 0; i < 4; i++) {
                int mr = wm*64 + i*16;
                af[i][0] = __float_as_uint(As[p][mr+g  ][s*8+tg  ]);
                af[i][1] = __float_as_uint(As[p][mr+g+8][s*8+tg  ]);
                af[i][2] = __float_as_uint(As[p][mr+g  ][s*8+tg+4]);
                af[i][3] = __float_as_uint(As[p][mr+g+8][s*8+tg+4]);
            }
            #pragma unroll
            for (int j = 0; j < 4; j++) {
                int nb = wn*32 + j*8;
                unsigned b0 = __float_as_uint(Bs[p][s*8+tg  ][nb+g]);
                unsigned b1 = __float_as_uint(Bs[p][s*8+tg+4][nb+g]);
                #pragma unroll
                for (int i = 0; i < 4; i++) MMA8(acc[i][j], af[i], b0, b1);
            }
        }
        if (hn) {
            st4cvt(&As[p^1][ar   ][ac], ra0);
            st4cvt(&As[p^1][ar+64][ac], ra1);
            st4cvt(&Bs[p^1][br  ][bc], rb0);
            st4cvt(&Bs[p^1][br+8][bc], rb1);
        }
        __syncthreads();
        p ^= 1;
    }

    #pragma unroll
    for (int i = 0; i < 4; i++) {
        int r = m0 + wm*64 + i*16 + g;
        #pragma unroll
        for (int j = 0; j < 4; j++) {
            int c = n0 + wn*32 + j*8 + 2*tg;
            C[r*N + c]         = acc[i][j][0];
            C[r*N + c + 1]     = acc[i][j][1];
            C[(r+8)*N + c]     = acc[i][j][2];
            C[(r+8)*N + c + 1] = acc[i][j][3];
        }
    }
}

// ============================================================================
// RoPE + scatter, pair-processed: one thread rotates (d, d+32) together.
// q -> Qr (scaled 1/8, tf32), k -> Kr (tf32), v -> Vt (tf32, transpose).
// ============================================================================
__global__ __launch_bounds__(256) void rope_scatter2()
{
    const int QP = BB*LL*NH*32;    // 2097152 rotation pairs (Q)
    const int KP = BB*LL*NKV*32;   //  524288 rotation pairs (K)
    const int VN = BB*LL*NKV*HD;   // 1048576 plain elements (V)
    const float C = -0.4152410118609203f;   // -log2(10000)/32
    int t = blockIdx.x * 256 + threadIdx.x;

    if (t < QP) {
        int i = t & 31, h = (t >> 5) & 15, l = (t >> 9) & 2047, b = t >> 20;
        const float* row = g_qkv + (b*LL + l)*NQKV + h*HD;
        float x1 = row[i], x2 = row[i + 32];
        float inv = exp2f((float)i * C);
        float sn, cs; sincosf((float)l * inv, &sn, &cs);
        float* o = g_Qr + ((b*NH + h)*LL + l)*HD;
        o[i]      = tf32r((x1*cs - x2*sn) * 0.125f);  // fold 1/sqrt(64)
        o[i + 32] = tf32r((x2*cs + x1*sn) * 0.125f);
    } else if (t < QP + KP) {
        int u = t - QP;
        int i = u & 31, h = (u >> 5) & 3, l = (u >> 7) & 2047, b = u >> 18;
        const float* row = g_qkv + (b*LL + l)*NQKV + 1024 + h*HD;
        float x1 = row[i], x2 = row[i + 32];
        float inv = exp2f((float)i * C);
        float sn, cs; sincosf((float)l * inv, &sn, &cs);
        float* o = g_Kr + ((b*NKV + h)*LL + l)*HD;
        o[i]      = tf32r(x1*cs - x2*sn);
        o[i + 32] = tf32r(x2*cs + x1*sn);
    } else if (t < QP + KP + VN) {
        int u = t - QP - KP;
        int l = u & 2047, d = (u >> 11) & 63, h = (u >> 17) & 3, b = u >> 19;
        g_Vt[((b*NKV + h)*HD + d)*LL + l] =
            tf32r(g_qkv[(b*LL + l)*NQKV + 1280 + h*HD + d]);
    }
}

// ============================================================================
// Sliding-window flash attention. CTA = (qtile of 64, head, batch), 4 warps.
// K/V tiles double-buffered in dynamic smem via cp.async (overlap w/ compute).
// ============================================================================
#define STG_F 8704                // floats per stage: K 64*68 + V 64*68
__global__ __launch_bounds__(128) void attn_kernel()
{
    extern __shared__ __align__(16) float dsm[];   // 2 * STG_F floats = 69632 B

    const int qt0 = blockIdx.x * 64;
    const int h   = blockIdx.y;
    const int b   = blockIdx.z;
    const int kv  = h >> 2;

    const int tid = threadIdx.x, w = tid >> 5, lane = tid & 31;
    const int g = lane >> 2, tg = lane & 3;

    const float* Qb = g_Qr + (size_t)((b*NH  + h )*LL)*HD;
    const float* Kb = g_Kr + (size_t)((b*NKV + kv)*LL)*HD;
    const float* Vb = g_Vt + (size_t)((b*NKV + kv)*HD)*LL;

    const int qr = qt0 + w*16;

    unsigned aq[8][4];
    #pragma unroll
    for (int s = 0; s < 8; s++) {
        aq[s][0] = __float_as_uint(Qb[(qr+g  )*HD + 8*s+tg  ]);
        aq[s][1] = __float_as_uint(Qb[(qr+g+8)*HD + 8*s+tg  ]);
        aq[s][2] = __float_as_uint(Qb[(qr+g  )*HD + 8*s+tg+4]);
        aq[s][3] = __float_as_uint(Qb[(qr+g+8)*HD + 8*s+tg+4]);
    }

    float o[8][4];
    #pragma unroll
    for (int dn = 0; dn < 8; dn++)
        #pragma unroll
        for (int e = 0; e < 4; e++) o[dn][e] = 0.f;
    float m0 = -1e30f, m1 = -1e30f, l0 = 0.f, l1 = 0.f;

    const int i0 = qt0 + w*16 + g;
    const int i1 = i0 + 8;

    int lo = qt0 - (WIN - 1); if (lo < 0) lo = 0;
    const int kt_lo = lo >> 6;
    const int kt_hi = qt0 >> 6;

    // async tile loader: 8 iterations x 2 cp.async per thread
    auto load_kv = [&](int kt, int p){
        const int j0 = kt << 6;
        float* base = dsm + p * STG_F;
        #pragma unroll
        for (int it = 0; it < 8; it++) {
            int idx = tid + it*128;
            int r = idx >> 4, c4 = (idx & 15) << 2;
            cpa16(base + r*68 + c4,        Kb + (j0+r)*HD + c4);
            cpa16(base + 4352 + r*68 + c4, Vb + r*LL + j0 + c4);
        }
    };

    load_kv(kt_lo, 0); CPA_COMMIT;

    int p = 0;
    for (int kt = kt_lo; kt <= kt_hi; kt++) {
        const int j0 = kt << 6;
        if (kt < kt_hi) { load_kv(kt+1, p^1); CPA_COMMIT; CPA_WAIT1; }
        else            { CPA_WAIT0; }
        __syncthreads();

        const float* Ks = dsm + p * STG_F;
        const float* Vs = Ks + 4352;

        // ---- S = Q K^T ----
        float sc[8][4];
        #pragma unroll
        for (int jn = 0; jn < 8; jn++) {
            sc[jn][0] = sc[jn][1] = sc[jn][2] = sc[jn][3] = 0.f;
            const int jb = jn*8 + g;
            #pragma unroll
            for (int s = 0; s < 8; s++) {
                unsigned b0 = __float_as_uint(Ks[jb*68 + 8*s+tg  ]);
                unsigned b1 = __float_as_uint(Ks[jb*68 + 8*s+tg+4]);
                MMA8(sc[jn], aq[s], b0, b1);
            }
        }

        // ---- mask only on edge tiles (window lower edge / causal edge) ----
        const bool domask = (kt == kt_lo) || (kt == kt_hi);
        if (domask) {
            #pragma unroll
            for (int jn = 0; jn < 8; jn++) {
                int j = j0 + jn*8 + 2*tg;
                if (!((j   <= i0) && (i0 - j     < WIN))) sc[jn][0] = -1e30f;
                if (!((j+1 <= i0) && (i0 - (j+1) < WIN))) sc[jn][1] = -1e30f;
                if (!((j   <= i1) && (i1 - j     < WIN))) sc[jn][2] = -1e30f;
                if (!((j+1 <= i1) && (i1 - (j+1) < WIN))) sc[jn][3] = -1e30f;
            }
        }

        // ---- online softmax (fp32) ----
        float mx0 = -1e30f, mx1 = -1e30f;
        #pragma unroll
        for (int jn = 0; jn < 8; jn++) {
            mx0 = fmaxf(mx0, fmaxf(sc[jn][0], sc[jn][1]));
            mx1 = fmaxf(mx1, fmaxf(sc[jn][2], sc[jn][3]));
        }
        mx0 = fmaxf(mx0, __shfl_xor_sync(0xffffffffu, mx0, 1));
        mx0 = fmaxf(mx0, __shfl_xor_sync(0xffffffffu, mx0, 2));
        mx1 = fmaxf(mx1, __shfl_xor_sync(0xffffffffu, mx1, 1));
        mx1 = fmaxf(mx1, __shfl_xor_sync(0xffffffffu, mx1, 2));

        const float f0  = (mx0 > -1e29f) ? 1.f : 0.f;   // fully-masked-row guard
        const float f1  = (mx1 > -1e29f) ? 1.f : 0.f;
        const float mn0 = fmaxf(m0, mx0), mn1 = fmaxf(m1, mx1);
        const float al0 = __expf(m0 - mn0), al1 = __expf(m1 - mn1);

        float rs0 = 0.f, rs1 = 0.f;
        #pragma unroll
        for (int jn = 0; jn < 8; jn++) {
            float p0 = f0 * __expf(sc[jn][0] - mn0);
            float p1 = f0 * __expf(sc[jn][1] - mn0);
            float p2 = f1 * __expf(sc[jn][2] - mn1);
            float p3 = f1 * __expf(sc[jn][3] - mn1);
            sc[jn][0] = p0; sc[jn][1] = p1; sc[jn][2] = p2; sc[jn][3] = p3;
            rs0 += p0 + p1; rs1 += p2 + p3;
        }
        rs0 += __shfl_xor_sync(0xffffffffu, rs0, 1);
        rs0 += __shfl_xor_sync(0xffffffffu, rs0, 2);
        rs1 += __shfl_xor_sync(0xffffffffu, rs1, 1);
        rs1 += __shfl_xor_sync(0xffffffffu, rs1, 2);

        l0 = l0*al0 + rs0;  l1 = l1*al1 + rs1;
        m0 = mn0;           m1 = mn1;

        #pragma unroll
        for (int dn = 0; dn < 8; dn++) {
            o[dn][0] *= al0; o[dn][1] *= al0;
            o[dn][2] *= al1; o[dn][3] *= al1;
        }

        // ---- O += P V : P C-layout -> A-layout via intra-group shuffles ----
        const int src1 = (g << 2) | (tg >> 1);
        const int src2 = src1 + 2;
        const bool odd = (tg & 1);
        #pragma unroll
        for (int s = 0; s < 8; s++) {
            float v00 = __shfl_sync(0xffffffffu, sc[s][0], src1);
            float v01 = __shfl_sync(0xffffffffu, sc[s][1], src1);
            float v10 = __shfl_sync(0xffffffffu, sc[s][2], src1);
            float v11 = __shfl_sync(0xffffffffu, sc[s][3], src1);
            float w00 = __shfl_sync(0xffffffffu, sc[s][0], src2);
            float w01 = __shfl_sync(0xffffffffu, sc[s][1], src2);
            float w10 = __shfl_sync(0xffffffffu, sc[s][2], src2);
            float w11 = __shfl_sync(0xffffffffu, sc[s][3], src2);
            unsigned pa[4];
            pa[0] = __float_as_uint(tf32r(odd ? v01 : v00));
            pa[1] = __float_as_uint(tf32r(odd ? v11 : v10));
            pa[2] = __float_as_uint(tf32r(odd ? w01 : w00));
            pa[3] = __float_as_uint(tf32r(odd ? w11 : w10));
            #pragma unroll
            for (int dn = 0; dn < 8; dn++) {
                unsigned b0 = __float_as_uint(Vs[(dn*8+g)*68 + 8*s+tg  ]);
                unsigned b1 = __float_as_uint(Vs[(dn*8+g)*68 + 8*s+tg+4]);
                MMA8(o[dn], pa, b0, b1);
            }
        }
        __syncthreads();   // all reads of stage p done before it is refilled
        p ^= 1;
    }

    // ---- epilogue: normalize, write O in [b, l, h*64] layout ----
    const float il0 = 1.f / l0;
    const float il1 = 1.f / l1;
    #pragma unroll
    for (int dn = 0; dn < 8; dn++) {
        int dc = h*HD + dn*8 + 2*tg;
        g_O[(b*LL + i0)*(NH*HD) + dc]     = o[dn][0] * il0;
        g_O[(b*LL + i0)*(NH*HD) + dc + 1] = o[dn][1] * il0;
        g_O[(b*LL + i1)*(NH*HD) + dc]     = o[dn][2] * il1;
        g_O[(b*LL + i1)*(NH*HD) + dc + 1] = o[dn][3] * il1;
    }
}

// ============================================================================
extern "C" void kernel_launch(void* const* d_in, const int* in_sizes, int n_in,
                              void* d_out, int out_size)
{
    const float* x  = (const float*)d_in[0];
    const float* Wq = (const float*)d_in[1];
    const float* Wk = (const float*)d_in[2];
    const float* Wv = (const float*)d_in[3];
    const float* Wo = (const float*)d_in[4];
    float* out = (float*)d_out;

    float *pW, *pqkv, *pO;
    cudaGetSymbolAddress((void**)&pW,   g_Wqkv);
    cudaGetSymbolAddress((void**)&pqkv, g_qkv);
    cudaGetSymbolAddress((void**)&pO,   g_O);

    const int ATTN_SMEM = 2 * STG_F * 4;   // 69632 B
    cudaFuncSetAttribute(attn_kernel,
                         cudaFuncAttributeMaxDynamicSharedMemorySize, ATTN_SMEM);

    const int M = BB * LL;  // 4096

    pack_w<<<(DDIM*NQKV/4 + 255)/256, 256>>>(Wq, Wk, Wv);
    gemm_tf32<<<dim3(NQKV/128, M/128), 256>>>(x, pW, pqkv, M, NQKV, DDIM);

    const int tot = BB*LL*NH*32 + BB*LL*NKV*32 + BB*LL*NKV*HD;  // 3670016
    rope_scatter2<<<(tot + 255)/256, 256>>>();

    attn_kernel<<<dim3(LL/64, NH, BB), 128, ATTN_SMEM>>>();

    gemm_tf32<<<dim3(DDIM/128, M/128), 256>>>(pO, Wo, out, M, DDIM, DDIM);
}